// round 13
// baseline (speedup 1.0000x reference)
#include <cuda_runtime.h>
#include <cstdint>
#include <math.h>

#define TT 8192
#define DD 2048
#define NE 8
#define FF 1408
#define KC 32              /* k-chunk (words) */
#define SROW 40            /* smem row stride (words); SROW%32==8 -> LDS.64 conflict-free */
#define THREADS 128
#define MAX_ASSIGN 17408   /* 136 * 128 */
#define MT 136             /* row tiles of 128 */

/* dynamic smem: per stage = 256 rows * SROW = 10240 words; 2 stages = 81920 bytes */
#define STG_SPAN 10240
#define OFF_B  5120        /* down: B region (128 rows) */
#define OFF_BG 5120        /* gateup: wg region (64 rows) */
#define OFF_BU 7680        /* gateup: wu region (64 rows) */
#define DYN_BYTES 81920

// ---------------- scratch (device globals only; no allocation) ----------------
__device__ int   g_tk_idx[TT*2];
__device__ float g_tk_w[TT*2];
__device__ int   g_offs[NE+1];
__device__ int   g_tok[MAX_ASSIGN];
__device__ int   g_slot[TT*2];
__device__ float g_act[(size_t)MAX_ASSIGN * FF];   // silu(h)*u, fp32
__device__ float g_y[(size_t)MAX_ASSIGN * DD];     // per-assignment down output

// ---------------- helpers ----------------
__device__ __forceinline__ uint32_t f2tf(float f){
    uint32_t u; asm("cvt.rna.tf32.f32 %0, %1;" : "=r"(u) : "f"(f)); return u;
}
__device__ __forceinline__ void mma_tf32(float c[4],
        uint32_t a0, uint32_t a1, uint32_t a2, uint32_t a3,
        uint32_t b0, uint32_t b1){
    asm volatile(
        "mma.sync.aligned.m16n8k8.row.col.f32.tf32.tf32.f32 "
        "{%0,%1,%2,%3}, {%4,%5,%6,%7}, {%8,%9}, {%0,%1,%2,%3};\n"
        : "+f"(c[0]), "+f"(c[1]), "+f"(c[2]), "+f"(c[3])
        : "r"(a0), "r"(a1), "r"(a2), "r"(a3), "r"(b0), "r"(b1));
}
// pair-permuted store: positions p..p+3 hold cols {c, c+4, c+1, c+5}
__device__ __forceinline__ void sts_pair(uint32_t* dst, float2 lo, float2 hi){
    *reinterpret_cast<uint4*>(dst) = make_uint4(f2tf(lo.x), f2tf(hi.x), f2tf(lo.y), f2tf(hi.y));
}

// ---------------- router: logits, top-2, renormalized weights ----------------
__global__ void router_kernel(const float* __restrict__ x,
                              const float* __restrict__ gw,
                              float* __restrict__ logits){
    int warp = (blockIdx.x * blockDim.x + threadIdx.x) >> 5;
    int lane = threadIdx.x & 31;
    if (warp >= TT) return;
    const float* xr = x + (size_t)warp * DD;
    float acc[NE];
#pragma unroll
    for (int e = 0; e < NE; e++) acc[e] = 0.f;
    for (int c = lane * 4; c < DD; c += 128){
        float4 xv = *reinterpret_cast<const float4*>(xr + c);
#pragma unroll
        for (int e = 0; e < NE; e++){
            float4 gv = *reinterpret_cast<const float4*>(gw + e*DD + c);
            acc[e] += xv.x*gv.x; acc[e] += xv.y*gv.y;
            acc[e] += xv.z*gv.z; acc[e] += xv.w*gv.w;
        }
    }
#pragma unroll
    for (int e = 0; e < NE; e++){
#pragma unroll
        for (int o = 16; o > 0; o >>= 1) acc[e] += __shfl_xor_sync(0xffffffffu, acc[e], o);
    }
    if (lane == 0){
#pragma unroll
        for (int e = 0; e < NE; e++) logits[(size_t)warp*NE + e] = acc[e];
        int i0 = 0; float l0 = acc[0];
#pragma unroll
        for (int e = 1; e < NE; e++) if (acc[e] > l0){ l0 = acc[e]; i0 = e; }
        int i1 = -1; float l1 = -1e30f;
#pragma unroll
        for (int e = 0; e < NE; e++) if (e != i0 && acc[e] > l1){ l1 = acc[e]; i1 = e; }
        float q  = expf(l1 - l0);
        float w0 = 1.f / (1.f + q);
        float w1 = q  / (1.f + q);
        g_tk_idx[warp*2+0] = i0; g_tk_idx[warp*2+1] = i1;
        g_tk_w [warp*2+0] = w0; g_tk_w [warp*2+1] = w1;
    }
}

// ---------------- build per-expert token lists (128-aligned segments) ----------------
__global__ void build_kernel(){
    __shared__ int cnt[NE];
    __shared__ int offs[NE+1];
    __shared__ int cur[NE];
    int tid = threadIdx.x;
    if (tid < NE) cnt[tid] = 0;
    __syncthreads();
    for (int i = tid; i < TT*2; i += blockDim.x) atomicAdd(&cnt[g_tk_idx[i]], 1);
    __syncthreads();
    if (tid == 0){
        int o = 0;
        for (int e = 0; e < NE; e++){ offs[e] = o; cur[e] = o; o += (cnt[e] + 127) & ~127; }
        offs[NE] = o;
        for (int e = 0; e <= NE; e++) g_offs[e] = offs[e];
    }
    __syncthreads();
    for (int i = tid; i < MAX_ASSIGN; i += blockDim.x) g_tok[i] = -1;
    __syncthreads();
    for (int i = tid; i < TT*2; i += blockDim.x){
        int e = g_tk_idx[i];
        int slot = atomicAdd(&cur[e], 1);
        g_tok[slot] = i >> 1;
        g_slot[i] = slot;
    }
}

// ---------------- GEMM 1: gathered x @ {w_gate,w_up}^T -> act = silu(h)*u ----------------
// Block: 128 rows x 64 F-cols; 4 warps; warp tile = 64 rows x 32 F-cols x BOTH h,u.
// KC=32, SROW=40, pair-permuted smem (LDS.64 fragments), double-buffered, 1 barrier/chunk.
__global__ __launch_bounds__(THREADS) void gateup_kernel(const float* __restrict__ x,
        const float* __restrict__ wg, const float* __restrict__ wu){
    extern __shared__ uint32_t dyn[];
    __shared__ int sTok[128];

    int fb   = blockIdx.x * 64;    // F-column base
    int row0 = blockIdx.y * 128;   // assignment-row tile
    int tid  = threadIdx.x;

    if (row0 >= g_offs[NE]) return;   // fully-dead padding tile (uniform)

    int e = 0;
#pragma unroll
    for (int i = 0; i < NE-1; i++) if (row0 >= g_offs[i+1]) e = i + 1;

    sTok[tid] = g_tok[row0 + tid];
    __syncthreads();

    int warp = tid >> 5, lane = tid & 31;
    int g = lane >> 2, tg = lane & 3;
    int tg2 = tg << 1;
    int wm = warp & 1, wn = warp >> 1;    // 2 m-tiles of 64 rows, 2 n-tiles of 32 F-cols

    // loader mapping: 8 threads per row; thread j covers cols {c,c+1} and {c+4,c+5}
    int rL = tid >> 3;                    // 0..15
    int j  = tid & 7;
    int cLo = ((j >> 1) << 3) + ((j & 1) << 1);   // 0,2,8,10,16,18,24,26
    int q  = j << 2;                      // permuted position base

    const float* aP[8];
#pragma unroll
    for (int i = 0; i < 8; i++){
        int tok = sTok[rL + 16*i];
        aP[i] = (tok >= 0) ? (x + (size_t)tok * DD + cLo) : (const float*)0;
    }
    const float* gB = wg + (size_t)(e*FF + fb + rL) * DD + cLo;   // rows rL+16i, i<4
    const float* uB = wu + (size_t)(e*FF + fb + rL) * DD + cLo;

    // fragment base offsets (word units), tg2 folded in
    int aOff[4];
#pragma unroll
    for (int mi = 0; mi < 4; mi++) aOff[mi] = (wm*64 + mi*16 + g)*SROW + tg2;
    int bOff[4];
#pragma unroll
    for (int ni = 0; ni < 4; ni++) bOff[ni] = (wn*32 + ni*8 + g)*SROW + tg2;
    int stOff = rL*SROW + q;

    float hC[4][4][4], uC[4][4][4];
#pragma unroll
    for (int mi = 0; mi < 4; mi++)
#pragma unroll
        for (int ni = 0; ni < 4; ni++)
#pragma unroll
            for (int jj = 0; jj < 4; jj++){ hC[mi][ni][jj] = 0.f; uC[mi][ni][jj] = 0.f; }

    // ---- prologue: fill stage 0 ----
    {
#pragma unroll
        for (int i = 0; i < 8; i++){
            float2 lo = make_float2(0.f,0.f), hi = make_float2(0.f,0.f);
            if (aP[i]){
                lo = *reinterpret_cast<const float2*>(aP[i]);
                hi = *reinterpret_cast<const float2*>(aP[i] + 4);
            }
            sts_pair(&dyn[stOff + (16*i)*SROW], lo, hi);
        }
#pragma unroll
        for (int i = 0; i < 4; i++){
            float2 glo = *reinterpret_cast<const float2*>(gB + (size_t)(16*i)*DD);
            float2 ghi = *reinterpret_cast<const float2*>(gB + (size_t)(16*i)*DD + 4);
            sts_pair(&dyn[OFF_BG + stOff + (16*i)*SROW], glo, ghi);
            float2 ulo = *reinterpret_cast<const float2*>(uB + (size_t)(16*i)*DD);
            float2 uhi = *reinterpret_cast<const float2*>(uB + (size_t)(16*i)*DD + 4);
            sts_pair(&dyn[OFF_BU + stOff + (16*i)*SROW], ulo, uhi);
        }
    }
    __syncthreads();

    const int NCH = DD / KC;   // 64
    for (int ck = 0; ck < NCH; ck++){
        int cb  = (ck & 1) * STG_SPAN;
        int nb_ = ((ck & 1) ^ 1) * STG_SPAN;
        bool more = (ck + 1) < NCH;
        int koff = (ck + 1) * KC;

        // wave 1: prefetch next A
        float2 loA[8], hiA[8];
        if (more){
#pragma unroll
            for (int i = 0; i < 8; i++){
                if (aP[i]){
                    loA[i] = *reinterpret_cast<const float2*>(aP[i] + koff);
                    hiA[i] = *reinterpret_cast<const float2*>(aP[i] + koff + 4);
                } else { loA[i] = make_float2(0.f,0.f); hiA[i] = make_float2(0.f,0.f); }
            }
        }
#pragma unroll
        for (int ks = 0; ks < 16; ks += 8){
            uint32_t a[4][4];
#pragma unroll
            for (int mi = 0; mi < 4; mi++){
                uint2 p0 = *reinterpret_cast<const uint2*>(&dyn[cb + aOff[mi] + ks]);
                uint2 p1 = *reinterpret_cast<const uint2*>(&dyn[cb + aOff[mi] + 8*SROW + ks]);
                a[mi][0] = p0.x; a[mi][1] = p1.x; a[mi][2] = p0.y; a[mi][3] = p1.y;
            }
#pragma unroll
            for (int ni = 0; ni < 4; ni++){
                uint2 pg = *reinterpret_cast<const uint2*>(&dyn[cb + OFF_BG + bOff[ni] + ks]);
                uint2 pu = *reinterpret_cast<const uint2*>(&dyn[cb + OFF_BU + bOff[ni] + ks]);
#pragma unroll
                for (int mi = 0; mi < 4; mi++){
                    mma_tf32(hC[mi][ni], a[mi][0],a[mi][1],a[mi][2],a[mi][3], pg.x, pg.y);
                    mma_tf32(uC[mi][ni], a[mi][0],a[mi][1],a[mi][2],a[mi][3], pu.x, pu.y);
                }
            }
        }
        // store next A; wave 2: prefetch next B
        float2 loG[4], hiG[4], loU[4], hiU[4];
        if (more){
#pragma unroll
            for (int i = 0; i < 8; i++)
                sts_pair(&dyn[nb_ + stOff + (16*i)*SROW], loA[i], hiA[i]);
#pragma unroll
            for (int i = 0; i < 4; i++){
                loG[i] = *reinterpret_cast<const float2*>(gB + (size_t)(16*i)*DD + koff);
                hiG[i] = *reinterpret_cast<const float2*>(gB + (size_t)(16*i)*DD + koff + 4);
                loU[i] = *reinterpret_cast<const float2*>(uB + (size_t)(16*i)*DD + koff);
                hiU[i] = *reinterpret_cast<const float2*>(uB + (size_t)(16*i)*DD + koff + 4);
            }
        }
#pragma unroll
        for (int ks = 16; ks < 32; ks += 8){
            uint32_t a[4][4];
#pragma unroll
            for (int mi = 0; mi < 4; mi++){
                uint2 p0 = *reinterpret_cast<const uint2*>(&dyn[cb + aOff[mi] + ks]);
                uint2 p1 = *reinterpret_cast<const uint2*>(&dyn[cb + aOff[mi] + 8*SROW + ks]);
                a[mi][0] = p0.x; a[mi][1] = p1.x; a[mi][2] = p0.y; a[mi][3] = p1.y;
            }
#pragma unroll
            for (int ni = 0; ni < 4; ni++){
                uint2 pg = *reinterpret_cast<const uint2*>(&dyn[cb + OFF_BG + bOff[ni] + ks]);
                uint2 pu = *reinterpret_cast<const uint2*>(&dyn[cb + OFF_BU + bOff[ni] + ks]);
#pragma unroll
                for (int mi = 0; mi < 4; mi++){
                    mma_tf32(hC[mi][ni], a[mi][0],a[mi][1],a[mi][2],a[mi][3], pg.x, pg.y);
                    mma_tf32(uC[mi][ni], a[mi][0],a[mi][1],a[mi][2],a[mi][3], pu.x, pu.y);
                }
            }
        }
        if (more){
#pragma unroll
            for (int i = 0; i < 4; i++){
                sts_pair(&dyn[nb_ + OFF_BG + stOff + (16*i)*SROW], loG[i], hiG[i]);
                sts_pair(&dyn[nb_ + OFF_BU + stOff + (16*i)*SROW], loU[i], hiU[i]);
            }
        }
        __syncthreads();
    }
    // epilogue: act = silu(h) * u
#pragma unroll
    for (int mi = 0; mi < 4; mi++)
#pragma unroll
        for (int ni = 0; ni < 4; ni++)
#pragma unroll
            for (int half = 0; half < 2; half++){
                int r    = row0 + wm*64 + mi*16 + g + half*8;
                int fcol = fb + wn*32 + ni*8 + tg*2;
                float h0 = hC[mi][ni][half*2+0], h1 = hC[mi][ni][half*2+1];
                float u0 = uC[mi][ni][half*2+0], u1 = uC[mi][ni][half*2+1];
                float v0 = h0 / (1.f + expf(-h0)) * u0;
                float v1 = h1 / (1.f + expf(-h1)) * u1;
                *reinterpret_cast<float2*>(&g_act[(size_t)r*FF + fcol]) = make_float2(v0, v1);
            }
}

// ---------------- GEMM 2: act @ w_down^T -> y (per-assignment rows, plain STG) ----------------
// Block: 128 rows x 128 D-cols; 4 warps; warp tile = 64 rows x 64 cols.
__global__ __launch_bounds__(THREADS) void down_kernel(const float* __restrict__ wd){
    extern __shared__ uint32_t dyn[];

    int nb   = blockIdx.x * 128;   // D-column base
    int row0 = blockIdx.y * 128;
    int tid  = threadIdx.x;

    if (row0 >= g_offs[NE]) return;   // fully-dead padding tile

    int e = 0;
#pragma unroll
    for (int i = 0; i < NE-1; i++) if (row0 >= g_offs[i+1]) e = i + 1;

    int warp = tid >> 5, lane = tid & 31;
    int g = lane >> 2, tg = lane & 3;
    int tg2 = tg << 1;
    int wm = warp & 1, wn = warp >> 1;   // 2 m-tiles of 64 rows, 2 n-tiles of 64 cols

    int rL = tid >> 3;                   // 0..15
    int j  = tid & 7;
    int cLo = ((j >> 1) << 3) + ((j & 1) << 1);
    int q  = j << 2;

    const float* aB = g_act + (size_t)(row0 + rL) * FF + cLo;   // rows rL+16i
    const float* bB = wd + (size_t)(e*DD + nb + rL) * FF + cLo;

    int aOff[4];
#pragma unroll
    for (int mi = 0; mi < 4; mi++) aOff[mi] = (wm*64 + mi*16 + g)*SROW + tg2;
    int bOff[8];
#pragma unroll
    for (int ni = 0; ni < 8; ni++) bOff[ni] = (wn*64 + ni*8 + g)*SROW + tg2;
    int stOff = rL*SROW + q;

    float C[4][8][4];
#pragma unroll
    for (int mi = 0; mi < 4; mi++)
#pragma unroll
        for (int ni = 0; ni < 8; ni++)
#pragma unroll
            for (int jj = 0; jj < 4; jj++) C[mi][ni][jj] = 0.f;

    // ---- prologue ----
    {
#pragma unroll
        for (int i = 0; i < 8; i++){
            float2 lo = *reinterpret_cast<const float2*>(aB + (size_t)(16*i)*FF);
            float2 hi = *reinterpret_cast<const float2*>(aB + (size_t)(16*i)*FF + 4);
            sts_pair(&dyn[stOff + (16*i)*SROW], lo, hi);
        }
#pragma unroll
        for (int i = 0; i < 8; i++){
            float2 lo = *reinterpret_cast<const float2*>(bB + (size_t)(16*i)*FF);
            float2 hi = *reinterpret_cast<const float2*>(bB + (size_t)(16*i)*FF + 4);
            sts_pair(&dyn[OFF_B + stOff + (16*i)*SROW], lo, hi);
        }
    }
    __syncthreads();

    const int NCH = FF / KC;   // 44
    for (int ck = 0; ck < NCH; ck++){
        int cb  = (ck & 1) * STG_SPAN;
        int nb_ = ((ck & 1) ^ 1) * STG_SPAN;
        bool more = (ck + 1) < NCH;
        int koff = (ck + 1) * KC;

        float2 loA[8], hiA[8];
        if (more){
#pragma unroll
            for (int i = 0; i < 8; i++){
                loA[i] = *reinterpret_cast<const float2*>(aB + (size_t)(16*i)*FF + koff);
                hiA[i] = *reinterpret_cast<const float2*>(aB + (size_t)(16*i)*FF + koff + 4);
            }
        }
#pragma unroll
        for (int ks = 0; ks < 16; ks += 8){
            uint32_t a[4][4];
#pragma unroll
            for (int mi = 0; mi < 4; mi++){
                uint2 p0 = *reinterpret_cast<const uint2*>(&dyn[cb + aOff[mi] + ks]);
                uint2 p1 = *reinterpret_cast<const uint2*>(&dyn[cb + aOff[mi] + 8*SROW + ks]);
                a[mi][0] = p0.x; a[mi][1] = p1.x; a[mi][2] = p0.y; a[mi][3] = p1.y;
            }
#pragma unroll
            for (int ni = 0; ni < 8; ni++){
                uint2 pb = *reinterpret_cast<const uint2*>(&dyn[cb + OFF_B + bOff[ni] + ks]);
#pragma unroll
                for (int mi = 0; mi < 4; mi++)
                    mma_tf32(C[mi][ni], a[mi][0],a[mi][1],a[mi][2],a[mi][3], pb.x, pb.y);
            }
        }
        float2 loB[8], hiB[8];
        if (more){
#pragma unroll
            for (int i = 0; i < 8; i++)
                sts_pair(&dyn[nb_ + stOff + (16*i)*SROW], loA[i], hiA[i]);
#pragma unroll
            for (int i = 0; i < 8; i++){
                loB[i] = *reinterpret_cast<const float2*>(bB + (size_t)(16*i)*FF + koff);
                hiB[i] = *reinterpret_cast<const float2*>(bB + (size_t)(16*i)*FF + koff + 4);
            }
        }
#pragma unroll
        for (int ks = 16; ks < 32; ks += 8){
            uint32_t a[4][4];
#pragma unroll
            for (int mi = 0; mi < 4; mi++){
                uint2 p0 = *reinterpret_cast<const uint2*>(&dyn[cb + aOff[mi] + ks]);
                uint2 p1 = *reinterpret_cast<const uint2*>(&dyn[cb + aOff[mi] + 8*SROW + ks]);
                a[mi][0] = p0.x; a[mi][1] = p1.x; a[mi][2] = p0.y; a[mi][3] = p1.y;
            }
#pragma unroll
            for (int ni = 0; ni < 8; ni++){
                uint2 pb = *reinterpret_cast<const uint2*>(&dyn[cb + OFF_B + bOff[ni] + ks]);
#pragma unroll
                for (int mi = 0; mi < 4; mi++)
                    mma_tf32(C[mi][ni], a[mi][0],a[mi][1],a[mi][2],a[mi][3], pb.x, pb.y);
            }
        }
        if (more){
#pragma unroll
            for (int i = 0; i < 8; i++)
                sts_pair(&dyn[nb_ + OFF_B + stOff + (16*i)*SROW], loB[i], hiB[i]);
        }
        __syncthreads();
    }
    // epilogue: plain STG of per-assignment rows (no atomics)
#pragma unroll
    for (int mi = 0; mi < 4; mi++)
#pragma unroll
        for (int half = 0; half < 2; half++){
            int rl = wm*64 + mi*16 + g + half*8;
            float* yrow = g_y + (size_t)(row0 + rl) * DD + nb;
#pragma unroll
            for (int ni = 0; ni < 8; ni++){
                int cb2 = wn*64 + ni*8 + tg*2;
                *reinterpret_cast<float2*>(yrow + cb2) =
                    make_float2(C[mi][ni][half*2+0], C[mi][ni][half*2+1]);
            }
        }
}

// ---------------- combine: out[t] = w0*y[slot0] + w1*y[slot1] (coalesced) ----------------
__global__ void combine_kernel(float* __restrict__ out){
    int gid = blockIdx.x * 256 + threadIdx.x;   // TT*512 threads, float4 each
    int t = gid >> 9;
    int d = (gid & 511) << 2;
    int s0 = g_slot[2*t], s1 = g_slot[2*t+1];
    float w0 = g_tk_w[2*t], w1 = g_tk_w[2*t+1];
    float4 y0 = *reinterpret_cast<const float4*>(&g_y[(size_t)s0*DD + d]);
    float4 y1 = *reinterpret_cast<const float4*>(&g_y[(size_t)s1*DD + d]);
    float4 r = make_float4(w0*y0.x + w1*y1.x, w0*y0.y + w1*y1.y,
                           w0*y0.z + w1*y1.z, w0*y0.w + w1*y1.w);
    *reinterpret_cast<float4*>(&out[(size_t)t*DD + d]) = r;
}

// ---------------- launch ----------------
extern "C" void kernel_launch(void* const* d_in, const int* in_sizes, int n_in,
                              void* d_out, int out_size){
    const float* x  = (const float*)d_in[0];   // [T, D]
    const float* gw = (const float*)d_in[1];   // [E, D]
    const float* wg = (const float*)d_in[2];   // [E, F, D]
    const float* wu = (const float*)d_in[3];   // [E, F, D]
    const float* wd = (const float*)d_in[4];   // [E, D, F]
    float* out    = (float*)d_out;             // [T*D] final, then [T*E] logits
    float* logits = out + (size_t)TT * DD;

    static int attr_done = 0;
    if (!attr_done){
        cudaFuncSetAttribute(gateup_kernel, cudaFuncAttributeMaxDynamicSharedMemorySize, DYN_BYTES);
        cudaFuncSetAttribute(down_kernel,   cudaFuncAttributeMaxDynamicSharedMemorySize, DYN_BYTES);
        attr_done = 1;
    }

    router_kernel<<<TT/8, 256>>>(x, gw, logits);
    build_kernel<<<1, 1024>>>();
    gateup_kernel<<<dim3(FF/64, MT), THREADS, DYN_BYTES>>>(x, wg, wu);
    down_kernel  <<<dim3(DD/128, MT), THREADS, DYN_BYTES>>>(wd);
    combine_kernel<<<TT*512/256, 256>>>(out);
}

// round 14
// speedup vs baseline: 1.2927x; 1.2927x over previous
#include <cuda_runtime.h>
#include <cstdint>
#include <math.h>

#define TT 8192
#define DD 2048
#define NE 8
#define FF 1408
#define KC 32              /* k-chunk (words) */
#define SROW 36            /* padded smem row stride (words): conflict-free STS+LDS */
#define THREADS 128
#define MAX_ASSIGN 17408   /* 136 * 128 */
#define MT 136
#define STG_SPAN 9216      /* words per stage (256 rows * 36) */
#define OFF_BG 4608
#define OFF_BU 6912
#define OFF_B  4608
#define NSTG 3
#define DYN_BYTES (NSTG*STG_SPAN*4)   /* 110592 */
#define WELEM (NE*FF*DD)              /* 23068672 */

// ---------------- scratch (device globals only; no allocation) ----------------
__device__ int   g_tk_idx[TT*2];
__device__ float g_tk_w[TT*2];
__device__ int   g_offs[NE+1];
__device__ int   g_tok[MAX_ASSIGN];
__device__ int   g_slot[TT*2];
__device__ uint32_t g_xt[(size_t)TT*DD];        // x pre-converted to tf32 bits
__device__ uint32_t g_wgt[WELEM];               // wg tf32
__device__ uint32_t g_wut[WELEM];               // wu tf32
__device__ uint32_t g_wdt[WELEM];               // wd tf32
__device__ uint32_t g_act[(size_t)MAX_ASSIGN * FF];  // silu(h)*u, tf32 bits
__device__ float g_y[(size_t)MAX_ASSIGN * DD];       // per-assignment down output

// ---------------- helpers ----------------
__device__ __forceinline__ uint32_t f2tf(float f){
    uint32_t u; asm("cvt.rna.tf32.f32 %0, %1;" : "=r"(u) : "f"(f)); return u;
}
__device__ __forceinline__ void mma_tf32(float c[4],
        uint32_t a0, uint32_t a1, uint32_t a2, uint32_t a3,
        uint32_t b0, uint32_t b1){
    asm volatile(
        "mma.sync.aligned.m16n8k8.row.col.f32.tf32.tf32.f32 "
        "{%0,%1,%2,%3}, {%4,%5,%6,%7}, {%8,%9}, {%0,%1,%2,%3};\n"
        : "+f"(c[0]), "+f"(c[1]), "+f"(c[2]), "+f"(c[3])
        : "r"(a0), "r"(a1), "r"(a2), "r"(a3), "r"(b0), "r"(b1));
}
__device__ __forceinline__ uint32_t smem_u32(const void* p){
    uint32_t a; asm("{ .reg .u64 t; cvta.to.shared.u64 t, %1; cvt.u32.u64 %0, t; }" : "=r"(a) : "l"(p)); return a;
}
__device__ __forceinline__ void cp16(uint32_t dst, const void* src){
    asm volatile("cp.async.cg.shared.global [%0], [%1], 16;" :: "r"(dst), "l"(src));
}
__device__ __forceinline__ void cp16z(uint32_t dst, const void* src){
    asm volatile("cp.async.cg.shared.global [%0], [%1], 16, 0;" :: "r"(dst), "l"(src));
}
#define CP_COMMIT() asm volatile("cp.async.commit_group;" ::: "memory")
#define CP_WAIT1()  asm volatile("cp.async.wait_group 1;" ::: "memory")

// ---------------- weight pre-convert: fp32 -> tf32 bits ----------------
__global__ void conv_kernel(const float4* __restrict__ wg,
                            const float4* __restrict__ wu,
                            const float4* __restrict__ wd){
    int i = blockIdx.x * blockDim.x + threadIdx.x;   // one float4 per thread
    if (i >= WELEM/4) return;
    float4 a = wg[i];
    reinterpret_cast<uint4*>(g_wgt)[i] = make_uint4(f2tf(a.x), f2tf(a.y), f2tf(a.z), f2tf(a.w));
    float4 b = wu[i];
    reinterpret_cast<uint4*>(g_wut)[i] = make_uint4(f2tf(b.x), f2tf(b.y), f2tf(b.z), f2tf(b.w));
    float4 c = wd[i];
    reinterpret_cast<uint4*>(g_wdt)[i] = make_uint4(f2tf(c.x), f2tf(c.y), f2tf(c.z), f2tf(c.w));
}

// ---------------- router: logits, top-2 weights; also emits tf32 x ----------------
__global__ void router_kernel(const float* __restrict__ x,
                              const float* __restrict__ gw,
                              float* __restrict__ logits){
    int warp = (blockIdx.x * blockDim.x + threadIdx.x) >> 5;
    int lane = threadIdx.x & 31;
    if (warp >= TT) return;
    const float* xr = x + (size_t)warp * DD;
    float acc[NE];
#pragma unroll
    for (int e = 0; e < NE; e++) acc[e] = 0.f;
    for (int c = lane * 4; c < DD; c += 128){
        float4 xv = *reinterpret_cast<const float4*>(xr + c);
        *reinterpret_cast<uint4*>(&g_xt[(size_t)warp*DD + c]) =
            make_uint4(f2tf(xv.x), f2tf(xv.y), f2tf(xv.z), f2tf(xv.w));
#pragma unroll
        for (int e = 0; e < NE; e++){
            float4 gv = *reinterpret_cast<const float4*>(gw + e*DD + c);
            acc[e] += xv.x*gv.x; acc[e] += xv.y*gv.y;
            acc[e] += xv.z*gv.z; acc[e] += xv.w*gv.w;
        }
    }
#pragma unroll
    for (int e = 0; e < NE; e++){
#pragma unroll
        for (int o = 16; o > 0; o >>= 1) acc[e] += __shfl_xor_sync(0xffffffffu, acc[e], o);
    }
    if (lane == 0){
#pragma unroll
        for (int e = 0; e < NE; e++) logits[(size_t)warp*NE + e] = acc[e];
        int i0 = 0; float l0 = acc[0];
#pragma unroll
        for (int e = 1; e < NE; e++) if (acc[e] > l0){ l0 = acc[e]; i0 = e; }
        int i1 = -1; float l1 = -1e30f;
#pragma unroll
        for (int e = 0; e < NE; e++) if (e != i0 && acc[e] > l1){ l1 = acc[e]; i1 = e; }
        float q  = expf(l1 - l0);
        float w0 = 1.f / (1.f + q);
        float w1 = q  / (1.f + q);
        g_tk_idx[warp*2+0] = i0; g_tk_idx[warp*2+1] = i1;
        g_tk_w [warp*2+0] = w0; g_tk_w [warp*2+1] = w1;
    }
}

// ---------------- build per-expert token lists (128-aligned segments) ----------------
__global__ void build_kernel(){
    __shared__ int cnt[NE];
    __shared__ int offs[NE+1];
    __shared__ int cur[NE];
    int tid = threadIdx.x;
    if (tid < NE) cnt[tid] = 0;
    __syncthreads();
    for (int i = tid; i < TT*2; i += blockDim.x) atomicAdd(&cnt[g_tk_idx[i]], 1);
    __syncthreads();
    if (tid == 0){
        int o = 0;
        for (int e = 0; e < NE; e++){ offs[e] = o; cur[e] = o; o += (cnt[e] + 127) & ~127; }
        offs[NE] = o;
        for (int e = 0; e <= NE; e++) g_offs[e] = offs[e];
    }
    __syncthreads();
    for (int i = tid; i < MAX_ASSIGN; i += blockDim.x) g_tok[i] = -1;
    __syncthreads();
    for (int i = tid; i < TT*2; i += blockDim.x){
        int e = g_tk_idx[i];
        int slot = atomicAdd(&cur[e], 1);
        g_tok[slot] = i >> 1;
        g_slot[i] = slot;
    }
}

// ---------------- GEMM 1: gathered x @ {w_gate,w_up}^T -> act = silu(h)*u ----------------
// Block: 128 rows x 64 F-cols; 4 warps; warp tile 64x32 x BOTH h,u.
// cp.async 3-stage pipeline; operands pre-converted tf32; KC=32, SROW=36.
__global__ __launch_bounds__(THREADS) void gateup_kernel(){
    extern __shared__ uint32_t dyn[];
    __shared__ int sTok[128];

    int fb   = blockIdx.x * 64;
    int row0 = blockIdx.y * 128;
    int tid  = threadIdx.x;

    if (row0 >= g_offs[NE]) return;   // fully-dead padding tile (uniform)

    int e = 0;
#pragma unroll
    for (int i = 0; i < NE-1; i++) if (row0 >= g_offs[i+1]) e = i + 1;

    sTok[tid] = g_tok[row0 + tid];
    __syncthreads();

    int warp = tid >> 5, lane = tid & 31;
    int g = lane >> 2, tg = lane & 3;
    int wm = warp & 1, wn = warp >> 1;

    int rL = tid >> 3;            // 0..15
    int cL = (tid & 7) << 2;      // 0,4,...,28
    uint32_t sb = smem_u32(dyn);

    const uint32_t* aSrc[8];
#pragma unroll
    for (int i = 0; i < 8; i++){
        int tok = sTok[rL + 16*i];
        aSrc[i] = (tok >= 0) ? (g_xt + (size_t)tok * DD + cL) : (const uint32_t*)0;
    }
    const uint32_t* gSrc = g_wgt + (size_t)(e*FF + fb + rL) * DD + cL;
    const uint32_t* uSrc = g_wut + (size_t)(e*FF + fb + rL) * DD + cL;

    uint32_t dA[8], dG[4], dU[4];
#pragma unroll
    for (int i = 0; i < 8; i++) dA[i] = ((rL + 16*i)*SROW + cL) * 4;
#pragma unroll
    for (int i = 0; i < 4; i++){
        dG[i] = (OFF_BG + (rL + 16*i)*SROW + cL) * 4;
        dU[i] = (OFF_BU + (rL + 16*i)*SROW + cL) * 4;
    }

    float hC[4][4][4], uC[4][4][4];
#pragma unroll
    for (int mi = 0; mi < 4; mi++)
#pragma unroll
        for (int ni = 0; ni < 4; ni++)
#pragma unroll
            for (int j = 0; j < 4; j++){ hC[mi][ni][j] = 0.f; uC[mi][ni][j] = 0.f; }

    const int NCH = DD / KC;   // 64
#define GU_LOAD(ck, st) do {                                              \
        uint32_t base = sb + (uint32_t)(st)*STG_SPAN*4;                   \
        int koff = (ck) * KC;                                             \
        _Pragma("unroll")                                                 \
        for (int i = 0; i < 8; i++){                                      \
            if (aSrc[i]) cp16(base + dA[i], aSrc[i] + koff);              \
            else         cp16z(base + dA[i], g_xt);                       \
        }                                                                 \
        _Pragma("unroll")                                                 \
        for (int i = 0; i < 4; i++){                                      \
            cp16(base + dG[i], gSrc + (size_t)(16*i)*DD + koff);          \
            cp16(base + dU[i], uSrc + (size_t)(16*i)*DD + koff);         \
        }                                                                 \
    } while(0)

    GU_LOAD(0, 0); CP_COMMIT();
    GU_LOAD(1, 1); CP_COMMIT();

    for (int ck = 0; ck < NCH; ck++){
        CP_WAIT1();
        __syncthreads();
        if (ck + 2 < NCH){
            int st = (ck + 2) % NSTG;
            GU_LOAD(ck + 2, st);
        }
        CP_COMMIT();
        int cb = (ck % NSTG) * STG_SPAN;
#pragma unroll
        for (int ks = 0; ks < KC; ks += 8){
            uint32_t a[4][4];
#pragma unroll
            for (int mi = 0; mi < 4; mi++){
                int r0 = (wm*64 + mi*16 + g)*SROW + cb;
                a[mi][0] = dyn[r0 + ks+tg];       a[mi][1] = dyn[r0 + 8*SROW + ks+tg];
                a[mi][2] = dyn[r0 + ks+tg+4];     a[mi][3] = dyn[r0 + 8*SROW + ks+tg+4];
            }
#pragma unroll
            for (int ni = 0; ni < 4; ni++){
                int br = (wn*32 + ni*8 + g)*SROW + cb;
                uint32_t bg0 = dyn[OFF_BG + br + ks+tg], bg1 = dyn[OFF_BG + br + ks+tg+4];
                uint32_t bu0 = dyn[OFF_BU + br + ks+tg], bu1 = dyn[OFF_BU + br + ks+tg+4];
#pragma unroll
                for (int mi = 0; mi < 4; mi++){
                    mma_tf32(hC[mi][ni], a[mi][0],a[mi][1],a[mi][2],a[mi][3], bg0, bg1);
                    mma_tf32(uC[mi][ni], a[mi][0],a[mi][1],a[mi][2],a[mi][3], bu0, bu1);
                }
            }
        }
    }
#undef GU_LOAD
    // epilogue: act = silu(h) * u, stored as tf32 bits
#pragma unroll
    for (int mi = 0; mi < 4; mi++)
#pragma unroll
        for (int ni = 0; ni < 4; ni++)
#pragma unroll
            for (int half = 0; half < 2; half++){
                int r    = row0 + wm*64 + mi*16 + g + half*8;
                int fcol = fb + wn*32 + ni*8 + tg*2;
                float h0 = hC[mi][ni][half*2+0], h1 = hC[mi][ni][half*2+1];
                float u0 = uC[mi][ni][half*2+0], u1 = uC[mi][ni][half*2+1];
                float v0 = h0 / (1.f + expf(-h0)) * u0;
                float v1 = h1 / (1.f + expf(-h1)) * u1;
                *reinterpret_cast<uint2*>(&g_act[(size_t)r*FF + fcol]) =
                    make_uint2(f2tf(v0), f2tf(v1));
            }
}

// ---------------- GEMM 2: act @ w_down^T -> y (per-assignment rows) ----------------
// Block: 128 rows x 128 D-cols; 4 warps; warp tile 64x64. cp.async 3-stage.
__global__ __launch_bounds__(THREADS) void down_kernel(){
    extern __shared__ uint32_t dyn[];

    int nb   = blockIdx.x * 128;
    int row0 = blockIdx.y * 128;
    int tid  = threadIdx.x;

    if (row0 >= g_offs[NE]) return;

    int e = 0;
#pragma unroll
    for (int i = 0; i < NE-1; i++) if (row0 >= g_offs[i+1]) e = i + 1;

    int warp = tid >> 5, lane = tid & 31;
    int g = lane >> 2, tg = lane & 3;
    int wm = warp & 1, wn = warp >> 1;

    int rL = tid >> 3;
    int cL = (tid & 7) << 2;
    uint32_t sb = smem_u32(dyn);

    const uint32_t* aSrc = g_act + (size_t)(row0 + rL) * FF + cL;
    const uint32_t* bSrc = g_wdt + (size_t)(e*DD + nb + rL) * FF + cL;

    uint32_t dA[8], dB[8];
#pragma unroll
    for (int i = 0; i < 8; i++){
        dA[i] = ((rL + 16*i)*SROW + cL) * 4;
        dB[i] = (OFF_B + (rL + 16*i)*SROW + cL) * 4;
    }

    float C[4][8][4];
#pragma unroll
    for (int mi = 0; mi < 4; mi++)
#pragma unroll
        for (int ni = 0; ni < 8; ni++)
#pragma unroll
            for (int j = 0; j < 4; j++) C[mi][ni][j] = 0.f;

    const int NCH = FF / KC;   // 44
#define DN_LOAD(ck, st) do {                                              \
        uint32_t base = sb + (uint32_t)(st)*STG_SPAN*4;                   \
        int koff = (ck) * KC;                                             \
        _Pragma("unroll")                                                 \
        for (int i = 0; i < 8; i++){                                      \
            cp16(base + dA[i], aSrc + (size_t)(16*i)*FF + koff);          \
            cp16(base + dB[i], bSrc + (size_t)(16*i)*FF + koff);         \
        }                                                                 \
    } while(0)

    DN_LOAD(0, 0); CP_COMMIT();
    DN_LOAD(1, 1); CP_COMMIT();

    for (int ck = 0; ck < NCH; ck++){
        CP_WAIT1();
        __syncthreads();
        if (ck + 2 < NCH){
            int st = (ck + 2) % NSTG;
            DN_LOAD(ck + 2, st);
        }
        CP_COMMIT();
        int cb = (ck % NSTG) * STG_SPAN;
#pragma unroll
        for (int ks = 0; ks < KC; ks += 8){
            uint32_t a[4][4], b[8][2];
#pragma unroll
            for (int mi = 0; mi < 4; mi++){
                int r0 = (wm*64 + mi*16 + g)*SROW + cb;
                a[mi][0] = dyn[r0 + ks+tg];       a[mi][1] = dyn[r0 + 8*SROW + ks+tg];
                a[mi][2] = dyn[r0 + ks+tg+4];     a[mi][3] = dyn[r0 + 8*SROW + ks+tg+4];
            }
#pragma unroll
            for (int ni = 0; ni < 8; ni++){
                int br = (wn*64 + ni*8 + g)*SROW + cb;
                b[ni][0] = dyn[OFF_B + br + ks+tg]; b[ni][1] = dyn[OFF_B + br + ks+tg+4];
            }
#pragma unroll
            for (int mi = 0; mi < 4; mi++)
#pragma unroll
                for (int ni = 0; ni < 8; ni++)
                    mma_tf32(C[mi][ni], a[mi][0],a[mi][1],a[mi][2],a[mi][3], b[ni][0], b[ni][1]);
        }
    }
#undef DN_LOAD
    // epilogue: plain STG of per-assignment rows (no atomics)
#pragma unroll
    for (int mi = 0; mi < 4; mi++)
#pragma unroll
        for (int half = 0; half < 2; half++){
            int rl = wm*64 + mi*16 + g + half*8;
            float* yrow = g_y + (size_t)(row0 + rl) * DD + nb;
#pragma unroll
            for (int ni = 0; ni < 8; ni++){
                int cb2 = wn*64 + ni*8 + tg*2;
                *reinterpret_cast<float2*>(yrow + cb2) =
                    make_float2(C[mi][ni][half*2+0], C[mi][ni][half*2+1]);
            }
        }
}

// ---------------- combine: out[t] = w0*y[slot0] + w1*y[slot1] (coalesced) ----------------
__global__ void combine_kernel(float* __restrict__ out){
    int gid = blockIdx.x * 256 + threadIdx.x;   // TT*512 threads, float4 each
    int t = gid >> 9;
    int d = (gid & 511) << 2;
    int s0 = g_slot[2*t], s1 = g_slot[2*t+1];
    float w0 = g_tk_w[2*t], w1 = g_tk_w[2*t+1];
    float4 y0 = *reinterpret_cast<const float4*>(&g_y[(size_t)s0*DD + d]);
    float4 y1 = *reinterpret_cast<const float4*>(&g_y[(size_t)s1*DD + d]);
    float4 r = make_float4(w0*y0.x + w1*y1.x, w0*y0.y + w1*y1.y,
                           w0*y0.z + w1*y1.z, w0*y0.w + w1*y1.w);
    *reinterpret_cast<float4*>(&out[(size_t)t*DD + d]) = r;
}

// ---------------- launch ----------------
extern "C" void kernel_launch(void* const* d_in, const int* in_sizes, int n_in,
                              void* d_out, int out_size){
    const float* x  = (const float*)d_in[0];   // [T, D]
    const float* gw = (const float*)d_in[1];   // [E, D]
    const float* wg = (const float*)d_in[2];   // [E, F, D]
    const float* wu = (const float*)d_in[3];   // [E, F, D]
    const float* wd = (const float*)d_in[4];   // [E, D, F]
    float* out    = (float*)d_out;             // [T*D] final, then [T*E] logits
    float* logits = out + (size_t)TT * DD;

    static int attr_done = 0;
    if (!attr_done){
        cudaFuncSetAttribute(gateup_kernel, cudaFuncAttributeMaxDynamicSharedMemorySize, DYN_BYTES);
        cudaFuncSetAttribute(down_kernel,   cudaFuncAttributeMaxDynamicSharedMemorySize, DYN_BYTES);
        attr_done = 1;
    }

    conv_kernel<<<(WELEM/4 + 255)/256, 256>>>((const float4*)wg, (const float4*)wu, (const float4*)wd);
    router_kernel<<<TT/8, 256>>>(x, gw, logits);
    build_kernel<<<1, 1024>>>();
    gateup_kernel<<<dim3(FF/64, MT), THREADS, DYN_BYTES>>>();
    down_kernel  <<<dim3(DD/128, MT), THREADS, DYN_BYTES>>>();
    combine_kernel<<<TT*512/256, 256>>>(out);
}

// round 16
// speedup vs baseline: 1.3647x; 1.0557x over previous
#include <cuda_runtime.h>
#include <cstdint>
#include <math.h>

#define TT 8192
#define DD 2048
#define NE 8
#define FF 1408
#define KC 32              /* k-chunk (words) */
#define SRA 36             /* row stride, unpermuted region (LDS.32 conflict-free) */
#define SRB 40             /* row stride, permuted regions (LDS.64 conflict-free) */
#define THREADS 128
#define MAX_ASSIGN 17408   /* 136 * 128 */
#define MT 136
/* gateup stage: A 128*36=4608 | BG 64*40=2560 @4608 | BU @7168 ; span 9728 w */
#define GU_SPAN 9728
#define OFF_BG 4608
#define OFF_BU 7168
/* down stage: A 128*40=5120 | B 128*40 @5120 ; span 10240 w */
#define DN_SPAN 10240
#define OFF_B  5120
#define DYN_BYTES (2*DN_SPAN*4)   /* 81920 */
#define WELEM (NE*FF*DD)

// ---------------- scratch (device globals only; no allocation) ----------------
__device__ int   g_tk_idx[TT*2];
__device__ float g_tk_w[TT*2];
__device__ int   g_offs[NE+1];
__device__ int   g_tok[MAX_ASSIGN];
__device__ int   g_slot[TT*2];
__device__ uint32_t g_xt[(size_t)TT*DD];        // x tf32 bits (unpermuted)
__device__ uint32_t g_wgt[WELEM];               // wg tf32, pair-permuted per 8-group
__device__ uint32_t g_wut[WELEM];               // wu tf32, pair-permuted
__device__ uint32_t g_wdt[WELEM];               // wd tf32, pair-permuted
__device__ uint32_t g_act[(size_t)MAX_ASSIGN * FF];  // silu(h)*u tf32, pair-permuted
__device__ float g_y[(size_t)MAX_ASSIGN * DD];       // per-assignment down output

// ---------------- helpers ----------------
__device__ __forceinline__ uint32_t f2tf(float f){
    uint32_t u; asm("cvt.rna.tf32.f32 %0, %1;" : "=r"(u) : "f"(f)); return u;
}
__device__ __forceinline__ void mma_tf32(float c[4],
        uint32_t a0, uint32_t a1, uint32_t a2, uint32_t a3,
        uint32_t b0, uint32_t b1){
    asm volatile(
        "mma.sync.aligned.m16n8k8.row.col.f32.tf32.tf32.f32 "
        "{%0,%1,%2,%3}, {%4,%5,%6,%7}, {%8,%9}, {%0,%1,%2,%3};\n"
        : "+f"(c[0]), "+f"(c[1]), "+f"(c[2]), "+f"(c[3])
        : "r"(a0), "r"(a1), "r"(a2), "r"(a3), "r"(b0), "r"(b1));
}
__device__ __forceinline__ uint32_t smem_u32(const void* p){
    uint32_t a; asm("{ .reg .u64 t; cvta.to.shared.u64 t, %1; cvt.u32.u64 %0, t; }" : "=r"(a) : "l"(p)); return a;
}
__device__ __forceinline__ void cp16(uint32_t dst, const void* src){
    asm volatile("cp.async.cg.shared.global [%0], [%1], 16;" :: "r"(dst), "l"(src));
}
__device__ __forceinline__ void cp16z(uint32_t dst, const void* src){
    asm volatile("cp.async.cg.shared.global [%0], [%1], 16, 0;" :: "r"(dst), "l"(src));
}
#define CP_COMMIT() asm volatile("cp.async.commit_group;" ::: "memory")
#define CP_WAIT0()  asm volatile("cp.async.wait_group 0;" ::: "memory")

// ---------------- weight pre-convert + pair-permute ----------------
// 8-group [c0..c7] stored as [c0,c4,c1,c5,c2,c6,c3,c7] (pos 2t<-col t, 2t+1<-col t+4)
__global__ void conv_kernel(const float4* __restrict__ wg,
                            const float4* __restrict__ wu,
                            const float4* __restrict__ wd){
    int i = blockIdx.x * blockDim.x + threadIdx.x;   // one 8-word group
    if (i >= WELEM/8) return;
#define PCONV(src, dst) do { \
        float4 lo = (src)[2*i], hi = (src)[2*i+1]; \
        reinterpret_cast<uint4*>(dst)[2*i] = \
            make_uint4(f2tf(lo.x), f2tf(hi.x), f2tf(lo.y), f2tf(hi.y)); \
        reinterpret_cast<uint4*>(dst)[2*i+1] = \
            make_uint4(f2tf(lo.z), f2tf(hi.z), f2tf(lo.w), f2tf(hi.w)); \
    } while(0)
    PCONV(wg, g_wgt);
    PCONV(wu, g_wut);
    PCONV(wd, g_wdt);
#undef PCONV
}

// ---------------- router: logits, top-2 weights; also emits tf32 x ----------------
__global__ void router_kernel(const float* __restrict__ x,
                              const float* __restrict__ gw,
                              float* __restrict__ logits){
    int warp = (blockIdx.x * blockDim.x + threadIdx.x) >> 5;
    int lane = threadIdx.x & 31;
    if (warp >= TT) return;
    const float* xr = x + (size_t)warp * DD;
    float acc[NE];
#pragma unroll
    for (int e = 0; e < NE; e++) acc[e] = 0.f;
    for (int c = lane * 4; c < DD; c += 128){
        float4 xv = *reinterpret_cast<const float4*>(xr + c);
        *reinterpret_cast<uint4*>(&g_xt[(size_t)warp*DD + c]) =
            make_uint4(f2tf(xv.x), f2tf(xv.y), f2tf(xv.z), f2tf(xv.w));
#pragma unroll
        for (int e = 0; e < NE; e++){
            float4 gv = *reinterpret_cast<const float4*>(gw + e*DD + c);
            acc[e] += xv.x*gv.x; acc[e] += xv.y*gv.y;
            acc[e] += xv.z*gv.z; acc[e] += xv.w*gv.w;
        }
    }
#pragma unroll
    for (int e = 0; e < NE; e++){
#pragma unroll
        for (int o = 16; o > 0; o >>= 1) acc[e] += __shfl_xor_sync(0xffffffffu, acc[e], o);
    }
    if (lane == 0){
#pragma unroll
        for (int e = 0; e < NE; e++) logits[(size_t)warp*NE + e] = acc[e];
        int i0 = 0; float l0 = acc[0];
#pragma unroll
        for (int e = 1; e < NE; e++) if (acc[e] > l0){ l0 = acc[e]; i0 = e; }
        int i1 = -1; float l1 = -1e30f;
#pragma unroll
        for (int e = 0; e < NE; e++) if (e != i0 && acc[e] > l1){ l1 = acc[e]; i1 = e; }
        float q  = expf(l1 - l0);
        float w0 = 1.f / (1.f + q);
        float w1 = q  / (1.f + q);
        g_tk_idx[warp*2+0] = i0; g_tk_idx[warp*2+1] = i1;
        g_tk_w [warp*2+0] = w0; g_tk_w [warp*2+1] = w1;
    }
}

// ---------------- build per-expert token lists (128-aligned segments) ----------------
__global__ void build_kernel(){
    __shared__ int cnt[NE];
    __shared__ int offs[NE+1];
    __shared__ int cur[NE];
    int tid = threadIdx.x;
    if (tid < NE) cnt[tid] = 0;
    __syncthreads();
    for (int i = tid; i < TT*2; i += blockDim.x) atomicAdd(&cnt[g_tk_idx[i]], 1);
    __syncthreads();
    if (tid == 0){
        int o = 0;
        for (int e = 0; e < NE; e++){ offs[e] = o; cur[e] = o; o += (cnt[e] + 127) & ~127; }
        offs[NE] = o;
        for (int e = 0; e <= NE; e++) g_offs[e] = offs[e];
    }
    __syncthreads();
    for (int i = tid; i < MAX_ASSIGN; i += blockDim.x) g_tok[i] = -1;
    __syncthreads();
    for (int i = tid; i < TT*2; i += blockDim.x){
        int e = g_tk_idx[i];
        int slot = atomicAdd(&cur[e], 1);
        g_tok[slot] = i >> 1;
        g_slot[i] = slot;
    }
}

// ---------------- GEMM 1: gathered x @ {w_gate,w_up}^T -> act = silu(h)*u ----------------
// Block 128 rows x 64 F; 4 warps; warp tile 64x32 x BOTH h,u.
// A unpermuted (LDS.32, SRA=36); B permuted (LDS.64, SRB=40). cp.async double-buffer.
__global__ __launch_bounds__(THREADS) void gateup_kernel(){
    extern __shared__ uint32_t dyn[];
    __shared__ int sTok[128];

    int fb   = blockIdx.x * 64;
    int row0 = blockIdx.y * 128;
    int tid  = threadIdx.x;

    if (row0 >= g_offs[NE]) return;

    int e = 0;
#pragma unroll
    for (int i = 0; i < NE-1; i++) if (row0 >= g_offs[i+1]) e = i + 1;

    sTok[tid] = g_tok[row0 + tid];
    __syncthreads();

    int warp = tid >> 5, lane = tid & 31;
    int g = lane >> 2, tg = lane & 3;
    int tg2 = tg << 1;
    int wm = warp & 1, wn = warp >> 1;

    int rL = tid >> 3;            // 0..15
    int cL = (tid & 7) << 2;      // 0,4,...,28
    uint32_t sb = smem_u32(dyn);

    const uint32_t* aSrc[8];
#pragma unroll
    for (int i = 0; i < 8; i++){
        int tok = sTok[rL + 16*i];
        aSrc[i] = (tok >= 0) ? (g_xt + (size_t)tok * DD + cL) : (const uint32_t*)0;
    }
    const uint32_t* gSrc = g_wgt + (size_t)(e*FF + fb + rL) * DD + cL;
    const uint32_t* uSrc = g_wut + (size_t)(e*FF + fb + rL) * DD + cL;

    uint32_t dA[8], dG[4], dU[4];
#pragma unroll
    for (int i = 0; i < 8; i++) dA[i] = ((rL + 16*i)*SRA + cL) * 4;
#pragma unroll
    for (int i = 0; i < 4; i++){
        dG[i] = (OFF_BG + (rL + 16*i)*SRB + cL) * 4;
        dU[i] = (OFF_BU + (rL + 16*i)*SRB + cL) * 4;
    }

    float hC[4][4][4], uC[4][4][4];
#pragma unroll
    for (int mi = 0; mi < 4; mi++)
#pragma unroll
        for (int ni = 0; ni < 4; ni++)
#pragma unroll
            for (int j = 0; j < 4; j++){ hC[mi][ni][j] = 0.f; uC[mi][ni][j] = 0.f; }

    const int NCH = DD / KC;   // 64
#define GU_LOAD(ck, st) do {                                              \
        uint32_t base = sb + (uint32_t)(st)*GU_SPAN*4;                    \
        int koff = (ck) * KC;                                             \
        _Pragma("unroll")                                                 \
        for (int i = 0; i < 8; i++){                                      \
            if (aSrc[i]) cp16(base + dA[i], aSrc[i] + koff);              \
            else         cp16z(base + dA[i], g_xt);                       \
        }                                                                 \
        _Pragma("unroll")                                                 \
        for (int i = 0; i < 4; i++){                                      \
            cp16(base + dG[i], gSrc + (size_t)(16*i)*DD + koff);          \
            cp16(base + dU[i], uSrc + (size_t)(16*i)*DD + koff);         \
        }                                                                 \
    } while(0)

    GU_LOAD(0, 0); CP_COMMIT();

    for (int ck = 0; ck < NCH; ck++){
        CP_WAIT0();
        __syncthreads();                 // all warps done with other stage + ck visible
        if (ck + 1 < NCH){ GU_LOAD(ck + 1, (ck + 1) & 1); CP_COMMIT(); }
        int cb = (ck & 1) * GU_SPAN;
#pragma unroll
        for (int ks = 0; ks < KC; ks += 8){
            uint32_t a[4][4];
#pragma unroll
            for (int mi = 0; mi < 4; mi++){
                int r0 = (wm*64 + mi*16 + g)*SRA + cb + ks + tg;
                a[mi][0] = dyn[r0];           a[mi][1] = dyn[r0 + 8*SRA];
                a[mi][2] = dyn[r0 + 4];       a[mi][3] = dyn[r0 + 8*SRA + 4];
            }
#pragma unroll
            for (int ni = 0; ni < 4; ni++){
                int br = (wn*32 + ni*8 + g)*SRB + cb + ks + tg2;
                uint2 pg = *reinterpret_cast<const uint2*>(&dyn[OFF_BG + br]);
                uint2 pu = *reinterpret_cast<const uint2*>(&dyn[OFF_BU + br]);
#pragma unroll
                for (int mi = 0; mi < 4; mi++){
                    mma_tf32(hC[mi][ni], a[mi][0],a[mi][1],a[mi][2],a[mi][3], pg.x, pg.y);
                    mma_tf32(uC[mi][ni], a[mi][0],a[mi][1],a[mi][2],a[mi][3], pu.x, pu.y);
                }
            }
        }
    }
#undef GU_LOAD
    // epilogue: act = silu(h)*u, stored PAIR-PERMUTED tf32
    int p0 = (tg < 2) ? (tg << 2) : (((tg - 2) << 2) + 1);   // permuted pos of col 2tg
#pragma unroll
    for (int mi = 0; mi < 4; mi++)
#pragma unroll
        for (int ni = 0; ni < 4; ni++)
#pragma unroll
            for (int half = 0; half < 2; half++){
                int r     = row0 + wm*64 + mi*16 + g + half*8;
                int fcol0 = fb + wn*32 + ni*8;
                float h0 = hC[mi][ni][half*2+0], h1 = hC[mi][ni][half*2+1];
                float u0 = uC[mi][ni][half*2+0], u1 = uC[mi][ni][half*2+1];
                float v0 = h0 / (1.f + expf(-h0)) * u0;
                float v1 = h1 / (1.f + expf(-h1)) * u1;
                g_act[(size_t)r*FF + fcol0 + p0    ] = f2tf(v0);
                g_act[(size_t)r*FF + fcol0 + p0 + 2] = f2tf(v1);
            }
}

// ---------------- GEMM 2: act @ w_down^T -> y ----------------
// Block 128 rows x 128 D; 4 warps; warp tile 64x64. Both operands permuted (LDS.64).
__global__ __launch_bounds__(THREADS) void down_kernel(){
    extern __shared__ uint32_t dyn[];

    int nb   = blockIdx.x * 128;
    int row0 = blockIdx.y * 128;
    int tid  = threadIdx.x;

    if (row0 >= g_offs[NE]) return;

    int e = 0;
#pragma unroll
    for (int i = 0; i < NE-1; i++) if (row0 >= g_offs[i+1]) e = i + 1;

    int warp = tid >> 5, lane = tid & 31;
    int g = lane >> 2, tg = lane & 3;
    int tg2 = tg << 1;
    int wm = warp & 1, wn = warp >> 1;

    int rL = tid >> 3;
    int cL = (tid & 7) << 2;
    uint32_t sb = smem_u32(dyn);

    const uint32_t* aSrc = g_act + (size_t)(row0 + rL) * FF + cL;
    const uint32_t* bSrc = g_wdt + (size_t)(e*DD + nb + rL) * FF + cL;

    uint32_t dA[8], dB[8];
#pragma unroll
    for (int i = 0; i < 8; i++){
        dA[i] = ((rL + 16*i)*SRB + cL) * 4;
        dB[i] = (OFF_B + (rL + 16*i)*SRB + cL) * 4;
    }

    float C[4][8][4];
#pragma unroll
    for (int mi = 0; mi < 4; mi++)
#pragma unroll
        for (int ni = 0; ni < 8; ni++)
#pragma unroll
            for (int j = 0; j < 4; j++) C[mi][ni][j] = 0.f;

    const int NCH = FF / KC;   // 44
#define DN_LOAD(ck, st) do {                                              \
        uint32_t base = sb + (uint32_t)(st)*DN_SPAN*4;                    \
        int koff = (ck) * KC;                                             \
        _Pragma("unroll")                                                 \
        for (int i = 0; i < 8; i++){                                      \
            cp16(base + dA[i], aSrc + (size_t)(16*i)*FF + koff);          \
            cp16(base + dB[i], bSrc + (size_t)(16*i)*FF + koff);         \
        }                                                                 \
    } while(0)

    DN_LOAD(0, 0); CP_COMMIT();

    for (int ck = 0; ck < NCH; ck++){
        CP_WAIT0();
        __syncthreads();
        if (ck + 1 < NCH){ DN_LOAD(ck + 1, (ck + 1) & 1); CP_COMMIT(); }
        int cb = (ck & 1) * DN_SPAN;
#pragma unroll
        for (int ks = 0; ks < KC; ks += 8){
            uint32_t a[4][4];
#pragma unroll
            for (int mi = 0; mi < 4; mi++){
                int r0 = (wm*64 + mi*16 + g)*SRB + cb + ks + tg2;
                uint2 q0 = *reinterpret_cast<const uint2*>(&dyn[r0]);
                uint2 q1 = *reinterpret_cast<const uint2*>(&dyn[r0 + 8*SRB]);
                a[mi][0] = q0.x; a[mi][1] = q1.x; a[mi][2] = q0.y; a[mi][3] = q1.y;
            }
#pragma unroll
            for (int ni = 0; ni < 8; ni++){
                int br = (wn*64 + ni*8 + g)*SRB + cb + ks + tg2;
                uint2 pb = *reinterpret_cast<const uint2*>(&dyn[OFF_B + br]);
#pragma unroll
                for (int mi = 0; mi < 4; mi++)
                    mma_tf32(C[mi][ni], a[mi][0],a[mi][1],a[mi][2],a[mi][3], pb.x, pb.y);
            }
        }
    }
#undef DN_LOAD
    // epilogue: plain STG of per-assignment rows (unpermuted fp32)
#pragma unroll
    for (int mi = 0; mi < 4; mi++)
#pragma unroll
        for (int half = 0; half < 2; half++){
            int rl = wm*64 + mi*16 + g + half*8;
            float* yrow = g_y + (size_t)(row0 + rl) * DD + nb;
#pragma unroll
            for (int ni = 0; ni < 8; ni++){
                int cb2 = wn*64 + ni*8 + tg*2;
                *reinterpret_cast<float2*>(yrow + cb2) =
                    make_float2(C[mi][ni][half*2+0], C[mi][ni][half*2+1]);
            }
        }
}

// ---------------- combine: out[t] = w0*y[slot0] + w1*y[slot1] (coalesced) ----------------
__global__ void combine_kernel(float* __restrict__ out){
    int gid = blockIdx.x * 256 + threadIdx.x;   // TT*512 threads, float4 each
    int t = gid >> 9;
    int d = (gid & 511) << 2;
    int s0 = g_slot[2*t], s1 = g_slot[2*t+1];
    float w0 = g_tk_w[2*t], w1 = g_tk_w[2*t+1];
    float4 y0 = *reinterpret_cast<const float4*>(&g_y[(size_t)s0*DD + d]);
    float4 y1 = *reinterpret_cast<const float4*>(&g_y[(size_t)s1*DD + d]);
    float4 r = make_float4(w0*y0.x + w1*y1.x, w0*y0.y + w1*y1.y,
                           w0*y0.z + w1*y1.z, w0*y0.w + w1*y1.w);
    *reinterpret_cast<float4*>(&out[(size_t)t*DD + d]) = r;
}

// ---------------- launch ----------------
extern "C" void kernel_launch(void* const* d_in, const int* in_sizes, int n_in,
                              void* d_out, int out_size){
    const float* x  = (const float*)d_in[0];   // [T, D]
    const float* gw = (const float*)d_in[1];   // [E, D]
    const float* wg = (const float*)d_in[2];   // [E, F, D]
    const float* wu = (const float*)d_in[3];   // [E, F, D]
    const float* wd = (const float*)d_in[4];   // [E, D, F]
    float* out    = (float*)d_out;             // [T*D] final, then [T*E] logits
    float* logits = out + (size_t)TT * DD;

    static int attr_done = 0;
    if (!attr_done){
        cudaFuncSetAttribute(gateup_kernel, cudaFuncAttributeMaxDynamicSharedMemorySize, DYN_BYTES);
        cudaFuncSetAttribute(down_kernel,   cudaFuncAttributeMaxDynamicSharedMemorySize, DYN_BYTES);
        attr_done = 1;
    }

    conv_kernel<<<(WELEM/8 + 255)/256, 256>>>((const float4*)wg, (const float4*)wu, (const float4*)wd);
    router_kernel<<<TT/8, 256>>>(x, gw, logits);
    build_kernel<<<1, 1024>>>();
    gateup_kernel<<<dim3(FF/64, MT), THREADS, DYN_BYTES>>>();
    down_kernel  <<<dim3(DD/128, MT), THREADS, DYN_BYTES>>>();
    combine_kernel<<<TT*512/256, 256>>>(out);
}